// round 10
// baseline (speedup 1.0000x reference)
#include <cuda_runtime.h>
#include <float.h>

// -------- scratch (no allocations; zero-init; tail resets) --------
#define MAXS 32768
#define MAXC 65536
__device__ int                g_off     [MAXS + 1]; // exclusive prefix sum + sentinel
__device__ int                g_chunkseg[MAXC];     // chunk -> containing segment
__device__ unsigned long long g_tden[MAXS];         // fixed-point (2^34) Σ e^t
__device__ unsigned long long g_msum[MAXS];         // fixed-point Σ e^m
__device__ unsigned long long g_dot [MAXS];         // fixed-point Σ e^t * m
__device__ unsigned int       g_flag;               // scan-done flag
__device__ unsigned int       g_done;               // finished-block counter (main)

#define SCALE     17179869184.0   // 2^34
#define INV_SCALE 0x1p-34f        // exact power-of-two

__device__ __forceinline__ void store_release_flag(unsigned int v) {
    asm volatile("st.global.release.gpu.b32 [%0], %1;" :: "l"(&g_flag), "r"(v) : "memory");
}
__device__ __forceinline__ unsigned int load_acquire_flag() {
    unsigned int v;
    asm volatile("ld.global.acquire.gpu.b32 %0, [%1];" : "=r"(v) : "l"(&g_flag) : "memory");
    return v;
}

// ============================================================
// Kernel 1: block 0 scans scope[] -> g_off; blocks 1.. map
// chunks -> segments after a lightweight acquire-poll.
// All blocks co-resident (tiny grid) => no deadlock.
// ============================================================
__global__ void __launch_bounds__(1024)
scan_map_kernel(const int* __restrict__ scope, int S, int N)
{
    const int tid  = threadIdx.x;
    const int lane = tid & 31;
    const int wid  = tid >> 5;

    if (blockIdx.x == 0) {
        // ---------------- scan ----------------
        __shared__ int s_w[32];
        if (tid == 0) g_off[S] = N;  // sentinel

        if (S == 16384) {
            const int4* s4 = reinterpret_cast<const int4*>(scope);
            int4 v[4];
            #pragma unroll
            for (int k = 0; k < 4; ++k) v[k] = s4[k * 1024 + tid];   // MLP=4, coalesced

            int carry = 0;
            #pragma unroll
            for (int k = 0; k < 4; ++k) {
                const int loc = v[k].x + v[k].y + v[k].z + v[k].w;

                int x = loc;
                #pragma unroll
                for (int off = 1; off < 32; off <<= 1) {
                    int y = __shfl_up_sync(0xffffffffu, x, off);
                    if (lane >= off) x += y;
                }
                if (lane == 31) s_w[wid] = x;
                __syncthreads();
                if (wid == 0) {
                    int w = s_w[lane];
                    #pragma unroll
                    for (int off = 1; off < 32; off <<= 1) {
                        int y = __shfl_up_sync(0xffffffffu, w, off);
                        if (lane >= off) w += y;
                    }
                    s_w[lane] = w;
                }
                __syncthreads();

                const int excl = ((wid == 0) ? 0 : s_w[wid - 1]) + (x - loc);
                const int tot  = s_w[31];

                int run = carry + excl;
                int4 o;
                o.x = run; run += v[k].x;
                o.y = run; run += v[k].y;
                o.z = run; run += v[k].z;
                o.w = run; run += v[k].w;
                reinterpret_cast<int4*>(g_off)[k * 1024 + tid] = o;

                carry += tot;
                __syncthreads();
            }
        } else {
            __shared__ int s_w2[32];
            const int per   = (S + 1023) / 1024;
            const int begin = min(tid * per, S);
            const int end   = min(begin + per, S);
            int local = 0;
            for (int i = begin; i < end; ++i) local += scope[i];
            int x = local;
            #pragma unroll
            for (int off = 1; off < 32; off <<= 1) {
                int y = __shfl_up_sync(0xffffffffu, x, off);
                if (lane >= off) x += y;
            }
            if (lane == 31) s_w2[wid] = x;
            __syncthreads();
            if (wid == 0) {
                int w = s_w2[lane];
                #pragma unroll
                for (int off = 1; off < 32; off <<= 1) {
                    int y = __shfl_up_sync(0xffffffffu, w, off);
                    if (lane >= off) w += y;
                }
                s_w2[lane] = w;
            }
            __syncthreads();
            int run = ((wid == 0) ? 0 : s_w2[wid - 1]) + (x - local);
            for (int i = begin; i < end; ++i) { g_off[i] = run; run += scope[i]; }
        }
        __syncthreads();
        if (tid == 0) store_release_flag(1u);
    } else {
        // ---------------- map (after scan) ----------------
        if (tid == 0) {
            while (load_acquire_flag() == 0u) { __nanosleep(64); }
        }
        __syncthreads();

        const int s = (blockIdx.x - 1) * 1024 + tid;
        if (s < S) {
            const int start = g_off[s];
            const int end   = g_off[s + 1];
            for (int c = (start + 255) >> 8; (c << 8) < end; ++c)
                g_chunkseg[c] = s;
        }
    }
}

// ============================================================
// Kernel 2: one WARP per 256-element chunk (balanced single pass)
// + last-BLOCK CE tail (deterministic, resets scratch).
// ============================================================
__global__ void __launch_bounds__(256)
main_kernel(const float* __restrict__ means,
            const float* __restrict__ targets,
            float* __restrict__ out,
            int N, int S)
{
    const int tid  = threadIdx.x;
    const int lane = tid & 31;
    const int warp = (blockIdx.x * 256 + tid) >> 5;
    const int base = warp * 256;

    __shared__ int   s_islast;
    __shared__ float s_red[256];

    if (base < N) {
        int s = g_chunkseg[warp];   // 1 load replaces binary search

        const int pos0 = base + lane * 4;
        const int pos1 = base + 128 + lane * 4;

        float e[8], w[8], d[8];
        if (base + 256 <= N) {
            const float4* tp = reinterpret_cast<const float4*>(targets);
            const float4* mp = reinterpret_cast<const float4*>(means);
            const int q = (base >> 2) + lane;
            float4 t0 = tp[q];        float4 t1 = tp[q + 32];
            float4 m0 = mp[q];        float4 m1 = mp[q + 32];
            float tt[8] = {t0.x,t0.y,t0.z,t0.w, t1.x,t1.y,t1.z,t1.w};
            float mm[8] = {m0.x,m0.y,m0.z,m0.w, m1.x,m1.y,m1.z,m1.w};
            #pragma unroll
            for (int j = 0; j < 8; ++j) {
                e[j] = __expf(tt[j]);
                w[j] = __expf(mm[j]);
                d[j] = e[j] * mm[j];
            }
        } else {
            #pragma unroll
            for (int j = 0; j < 8; ++j) {
                int p = (j < 4) ? (pos0 + j) : (pos1 + j - 4);
                float tv = (p < N) ? targets[p] : 0.f;
                float mv = (p < N) ? means[p]   : 0.f;
                e[j] = __expf(tv);
                w[j] = __expf(mv);
                d[j] = e[j] * mv;
            }
        }

        const int last = min(base + 255, N - 1);
        int lower = g_off[s];
        for (;;) {
            const int next = g_off[s + 1];  // sentinel guarantees validity
            float a = 0.f, b = 0.f, c = 0.f;
            #pragma unroll
            for (int j = 0; j < 8; ++j) {
                const int p = (j < 4) ? (pos0 + j) : (pos1 + j - 4);
                if (p >= lower && p < next) { a += e[j]; b += w[j]; c += d[j]; }
            }
            #pragma unroll
            for (int o = 16; o; o >>= 1) {
                a += __shfl_xor_sync(0xffffffffu, a, o);
                b += __shfl_xor_sync(0xffffffffu, b, o);
                c += __shfl_xor_sync(0xffffffffu, c, o);
            }
            if (lane == 0) {
                atomicAdd(&g_tden[s], (unsigned long long)__double2ll_rn((double)a * SCALE));
                atomicAdd(&g_msum[s], (unsigned long long)__double2ll_rn((double)b * SCALE));
                atomicAdd(&g_dot [s], (unsigned long long)__double2ll_rn((double)c * SCALE));
            }
            if (next > last) break;
            lower = next;
            ++s;
        }
    }

    // ---------------- last-block CE tail ----------------
    __syncthreads();
    if (tid == 0) {
        __threadfence();                       // release this block's atomics
        unsigned int prev = atomicAdd(&g_done, 1u);
        s_islast = (prev == gridDim.x - 1) ? 1 : 0;
    }
    __syncthreads();
    if (!s_islast) return;
    __threadfence();                           // acquire: all blocks' sums final

    float part = 0.f;
    for (int seg = tid; seg < S; seg += 256) {
        long long tdq = (long long)__ldcg(&g_tden[seg]);
        if (tdq > 0) {
            float td = __ll2float_rn(tdq);                                   // scale cancels
            float ms = __ll2float_rn((long long)__ldcg(&g_msum[seg])) * INV_SCALE;
            float dt = __ll2float_rn((long long)__ldcg(&g_dot [seg]));
            part += dt / td - __logf(ms);
        }
        g_tden[seg] = 0ull; g_msum[seg] = 0ull; g_dot[seg] = 0ull;   // reset for next replay
    }
    s_red[tid] = part;
    __syncthreads();
    #pragma unroll
    for (int st = 128; st; st >>= 1) {
        if (tid < st) s_red[tid] += s_red[tid + st];
        __syncthreads();
    }
    if (tid == 0) {
        out[0] = -s_red[0] / (float)S;
        g_done = 0u;          // reset for next replay
        store_release_flag(0u);
    }
}

// ============================================================
extern "C" void kernel_launch(void* const* d_in, const int* in_sizes, int n_in,
                              void* d_out, int out_size)
{
    const float* means   = (const float*)d_in[0];
    const int*   scope   = (const int*)  d_in[1];
    const float* targets = (const float*)d_in[2];
    const int N = in_sizes[0];
    const int S = in_sizes[1];

    const int mapBlocks = (S + 1023) / 1024;
    scan_map_kernel<<<1 + mapBlocks, 1024>>>(scope, S, N);

    const int nWarps  = (N + 255) / 256;
    const int nBlocks = (nWarps + 7) / 8;
    main_kernel<<<nBlocks, 256>>>(means, targets, (float*)d_out, N, S);
}

// round 11
// speedup vs baseline: 2.7637x; 2.7637x over previous
#include <cuda_runtime.h>
#include <float.h>

// -------- scratch (no allocations; zero-init; ce_kernel resets) --------
#define MAXS 32768
#define MAXC 65536
__device__ int                g_off     [MAXS + 1]; // exclusive prefix sum + sentinel
__device__ int                g_chunkseg[MAXC];     // chunk -> containing segment
__device__ unsigned long long g_tden[MAXS];         // fixed-point (2^34) Σ e^t
__device__ unsigned long long g_msum[MAXS];         // fixed-point Σ e^m
__device__ unsigned long long g_dot [MAXS];         // fixed-point Σ e^t * m
__device__ unsigned long long g_acc;                // fixed-point global Σ ce
__device__ unsigned int       g_flag;               // scan-done flag
__device__ unsigned int       g_done;               // finished-block counter (ce)

#define SCALE     17179869184.0   // 2^34
#define INV_SCALE 0x1p-34f        // exact power-of-two

__device__ __forceinline__ void store_release_flag(unsigned int v) {
    asm volatile("st.global.release.gpu.b32 [%0], %1;" :: "l"(&g_flag), "r"(v) : "memory");
}
__device__ __forceinline__ unsigned int load_acquire_flag() {
    unsigned int v;
    asm volatile("ld.global.acquire.gpu.b32 %0, [%1];" : "=r"(v) : "l"(&g_flag) : "memory");
    return v;
}

// ============================================================
// Kernel 1: block 0 scans scope[] -> g_off; blocks 1.. fill the
// chunk->segment map after a lightweight acquire-poll (1 poller
// per block). All 17 blocks co-resident => no deadlock.
// ============================================================
__global__ void __launch_bounds__(1024)
scan_map_kernel(const int* __restrict__ scope, int S, int N)
{
    const int tid  = threadIdx.x;
    const int lane = tid & 31;
    const int wid  = tid >> 5;

    if (blockIdx.x == 0) {
        // ---------------- scan ----------------
        __shared__ int s_w[32];
        if (tid == 0) g_off[S] = N;  // sentinel

        if (S == 16384) {
            const int4* s4 = reinterpret_cast<const int4*>(scope);
            int4 v[4];
            #pragma unroll
            for (int k = 0; k < 4; ++k) v[k] = s4[k * 1024 + tid];   // MLP=4, coalesced

            int carry = 0;
            #pragma unroll
            for (int k = 0; k < 4; ++k) {
                const int loc = v[k].x + v[k].y + v[k].z + v[k].w;

                int x = loc;
                #pragma unroll
                for (int off = 1; off < 32; off <<= 1) {
                    int y = __shfl_up_sync(0xffffffffu, x, off);
                    if (lane >= off) x += y;
                }
                if (lane == 31) s_w[wid] = x;
                __syncthreads();
                if (wid == 0) {
                    int w = s_w[lane];
                    #pragma unroll
                    for (int off = 1; off < 32; off <<= 1) {
                        int y = __shfl_up_sync(0xffffffffu, w, off);
                        if (lane >= off) w += y;
                    }
                    s_w[lane] = w;
                }
                __syncthreads();

                const int excl = ((wid == 0) ? 0 : s_w[wid - 1]) + (x - loc);
                const int tot  = s_w[31];

                int run = carry + excl;
                int4 o;
                o.x = run; run += v[k].x;
                o.y = run; run += v[k].y;
                o.z = run; run += v[k].z;
                o.w = run; run += v[k].w;
                reinterpret_cast<int4*>(g_off)[k * 1024 + tid] = o;

                carry += tot;
                __syncthreads();
            }
        } else {
            __shared__ int s_w2[32];
            const int per   = (S + 1023) / 1024;
            const int begin = min(tid * per, S);
            const int end   = min(begin + per, S);
            int local = 0;
            for (int i = begin; i < end; ++i) local += scope[i];
            int x = local;
            #pragma unroll
            for (int off = 1; off < 32; off <<= 1) {
                int y = __shfl_up_sync(0xffffffffu, x, off);
                if (lane >= off) x += y;
            }
            if (lane == 31) s_w2[wid] = x;
            __syncthreads();
            if (wid == 0) {
                int w = s_w2[lane];
                #pragma unroll
                for (int off = 1; off < 32; off <<= 1) {
                    int y = __shfl_up_sync(0xffffffffu, w, off);
                    if (lane >= off) w += y;
                }
                s_w2[lane] = w;
            }
            __syncthreads();
            int run = ((wid == 0) ? 0 : s_w2[wid - 1]) + (x - local);
            for (int i = begin; i < end; ++i) { g_off[i] = run; run += scope[i]; }
        }
        __syncthreads();
        if (tid == 0) store_release_flag(1u);
    } else {
        // ---------------- map (after scan) ----------------
        if (tid == 0) {
            while (load_acquire_flag() == 0u) { __nanosleep(64); }
        }
        __syncthreads();

        const int s = (blockIdx.x - 1) * 1024 + tid;
        if (s < S) {
            const int start = g_off[s];
            const int end   = g_off[s + 1];
            for (int c = (start + 255) >> 8; (c << 8) < end; ++c)
                g_chunkseg[c] = s;
        }
    }
}

// ============================================================
// Kernel 2: one WARP per 256-element chunk (balanced single pass).
// NO tail, NO fences, NO single-address atomics — keep it pure.
// ============================================================
__global__ void __launch_bounds__(256)
main_kernel(const float* __restrict__ means,
            const float* __restrict__ targets,
            int N, int S)
{
    const int lane = threadIdx.x & 31;
    const int warp = (blockIdx.x * 256 + threadIdx.x) >> 5;
    const int base = warp * 256;
    if (base >= N) return;

    int s = g_chunkseg[warp];   // 1 load replaces binary search

    const int pos0 = base + lane * 4;
    const int pos1 = base + 128 + lane * 4;

    float e[8], w[8], d[8];
    if (base + 256 <= N) {
        const float4* tp = reinterpret_cast<const float4*>(targets);
        const float4* mp = reinterpret_cast<const float4*>(means);
        const int q = (base >> 2) + lane;
        float4 t0 = tp[q];        float4 t1 = tp[q + 32];
        float4 m0 = mp[q];        float4 m1 = mp[q + 32];
        float tt[8] = {t0.x,t0.y,t0.z,t0.w, t1.x,t1.y,t1.z,t1.w};
        float mm[8] = {m0.x,m0.y,m0.z,m0.w, m1.x,m1.y,m1.z,m1.w};
        #pragma unroll
        for (int j = 0; j < 8; ++j) {
            e[j] = __expf(tt[j]);
            w[j] = __expf(mm[j]);
            d[j] = e[j] * mm[j];
        }
    } else {
        #pragma unroll
        for (int j = 0; j < 8; ++j) {
            int p = (j < 4) ? (pos0 + j) : (pos1 + j - 4);
            float tv = (p < N) ? targets[p] : 0.f;
            float mv = (p < N) ? means[p]   : 0.f;
            e[j] = __expf(tv);
            w[j] = __expf(mv);
            d[j] = e[j] * mv;
        }
    }

    const int last = min(base + 255, N - 1);
    int lower = g_off[s];
    for (;;) {
        const int next = g_off[s + 1];  // sentinel guarantees validity
        float a = 0.f, b = 0.f, c = 0.f;
        #pragma unroll
        for (int j = 0; j < 8; ++j) {
            const int p = (j < 4) ? (pos0 + j) : (pos1 + j - 4);
            if (p >= lower && p < next) { a += e[j]; b += w[j]; c += d[j]; }
        }
        #pragma unroll
        for (int o = 16; o; o >>= 1) {
            a += __shfl_xor_sync(0xffffffffu, a, o);
            b += __shfl_xor_sync(0xffffffffu, b, o);
            c += __shfl_xor_sync(0xffffffffu, c, o);
        }
        if (lane == 0) {
            atomicAdd(&g_tden[s], (unsigned long long)__double2ll_rn((double)a * SCALE));
            atomicAdd(&g_msum[s], (unsigned long long)__double2ll_rn((double)b * SCALE));
            atomicAdd(&g_dot [s], (unsigned long long)__double2ll_rn((double)c * SCALE));
        }
        if (next > last) break;
        lower = next;
        ++s;
    }
}

// ============================================================
// Kernel 3: per-segment CE (fp32) + deterministic reduce + reset
// ============================================================
__global__ void __launch_bounds__(256)
ce_kernel(float* __restrict__ out, int S)
{
    const int tid  = threadIdx.x;
    const int lane = tid & 31;
    const int wid  = tid >> 5;
    const int seg  = blockIdx.x * 256 + tid;

    float ce = 0.f;
    if (seg < S) {
        long long tdq = (long long)g_tden[seg];
        float td = __ll2float_rn(tdq);                                 // 2^34 scale cancels
        float ms = __ll2float_rn((long long)g_msum[seg]) * INV_SCALE;  // exact pow2 scale
        float dt = __ll2float_rn((long long)g_dot [seg]);
        if (tdq > 0) ce = dt / td - __logf(ms);
        g_tden[seg] = 0ull; g_msum[seg] = 0ull; g_dot[seg] = 0ull;     // reset for next replay
    }

    __shared__ float sm[8];
    float v = ce;
    #pragma unroll
    for (int o = 16; o; o >>= 1) v += __shfl_xor_sync(0xffffffffu, v, o);
    if (lane == 0) sm[wid] = v;
    __syncthreads();
    if (wid == 0) {
        v = (lane < 8) ? sm[lane] : 0.f;
        #pragma unroll
        for (int o = 4; o; o >>= 1) v += __shfl_xor_sync(0xffffffffu, v, o);
        if (lane == 0) {
            atomicAdd(&g_acc, (unsigned long long)__double2ll_rn((double)v * SCALE));
            __threadfence();
            unsigned int prev = atomicAdd(&g_done, 1u);
            if (prev == gridDim.x - 1) {
                unsigned long long tot = atomicAdd(&g_acc, 0ull);
                double sum = (double)(long long)tot / SCALE;
                out[0] = (float)(-sum / (double)S);
                g_acc  = 0ull;   // reset for next replay
                g_done = 0u;
                g_flag = 0u;     // re-arm scan/map handshake
                __threadfence();
            }
        }
    }
}

// ============================================================
extern "C" void kernel_launch(void* const* d_in, const int* in_sizes, int n_in,
                              void* d_out, int out_size)
{
    const float* means   = (const float*)d_in[0];
    const int*   scope   = (const int*)  d_in[1];
    const float* targets = (const float*)d_in[2];
    const int N = in_sizes[0];
    const int S = in_sizes[1];

    const int mapBlocks = (S + 1023) / 1024;
    scan_map_kernel<<<1 + mapBlocks, 1024>>>(scope, S, N);

    const int nWarps  = (N + 255) / 256;
    const int nBlocks = (nWarps + 7) / 8;
    main_kernel<<<nBlocks, 256>>>(means, targets, N, S);

    ce_kernel<<<(S + 255) / 256, 256>>>((float*)d_out, S);
}

// round 12
// speedup vs baseline: 3.0260x; 1.0949x over previous
#include <cuda_runtime.h>
#include <float.h>

// -------- scratch (no allocations; zero-init; ce_kernel resets) --------
#define MAXS 32768
#define MAXC 65536
#define MAXB 32                                    // max scan blocks (MAXS/1024)
__device__ int                g_off     [MAXS + 1]; // exclusive prefix sum + sentinel
__device__ int                g_chunkseg[MAXC];     // chunk -> containing segment
__device__ int                g_tilesum [MAXB];     // per-block scope totals
__device__ unsigned long long g_tden[MAXS];         // fixed-point (2^34) Σ e^t
__device__ unsigned long long g_msum[MAXS];         // fixed-point Σ e^m
__device__ unsigned long long g_dot [MAXS];         // fixed-point Σ e^t * m
__device__ unsigned long long g_acc;                // fixed-point global Σ ce
__device__ unsigned int       g_scnt;               // scan phase-1 arrival counter
__device__ unsigned int       g_done;               // finished-block counter (ce)

#define SCALE     17179869184.0   // 2^34
#define INV_SCALE 0x1p-34f        // exact power-of-two

__device__ __forceinline__ unsigned int load_acquire_u32(const unsigned int* p) {
    unsigned int v;
    asm volatile("ld.global.acquire.gpu.b32 %0, [%1];" : "=r"(v) : "l"(p) : "memory");
    return v;
}

// ============================================================
// Kernel 1: multi-block scan + map. One segment per thread.
//   phase 1: block scan of its 1024 scope values; publish tile total
//   sync   : 1 poller/block on arrival counter (all blocks resident)
//   phase 2: add prior tile totals -> g_off; fill chunk->segment map
// ============================================================
__global__ void __launch_bounds__(1024)
scan_map_kernel(const int* __restrict__ scope, int S, int N)
{
    __shared__ int s_w[32];
    const int tid  = threadIdx.x;
    const int lane = tid & 31;
    const int wid  = tid >> 5;
    const int b    = blockIdx.x;
    const int s    = b * 1024 + tid;
    const int B    = gridDim.x;

    // ---- phase 1: intra-block exclusive scan ----
    const int len = (s < S) ? scope[s] : 0;

    int x = len;
    #pragma unroll
    for (int off = 1; off < 32; off <<= 1) {
        int y = __shfl_up_sync(0xffffffffu, x, off);
        if (lane >= off) x += y;
    }
    if (lane == 31) s_w[wid] = x;
    __syncthreads();
    if (wid == 0) {
        int w = s_w[lane];
        #pragma unroll
        for (int off = 1; off < 32; off <<= 1) {
            int y = __shfl_up_sync(0xffffffffu, w, off);
            if (lane >= off) w += y;
        }
        s_w[lane] = w;
    }
    __syncthreads();

    const int intra_excl = ((wid == 0) ? 0 : s_w[wid - 1]) + (x - len);
    const int block_tot  = s_w[31];

    // publish tile total, arrive
    if (tid == 0) {
        g_tilesum[b] = block_tot;
        __threadfence();                 // release (once per block)
        atomicAdd(&g_scnt, 1u);
    }

    // ---- sync: wait for all tile totals ----
    if (tid == 0) {
        while (load_acquire_u32(&g_scnt) < (unsigned int)B) { __nanosleep(64); }
    }
    __syncthreads();

    // ---- phase 2: global offset + map fill ----
    int tile_prefix = 0;
    for (int j = 0; j < b; ++j) tile_prefix += g_tilesum[j];   // <=31 L1-broadcast reads

    if (s < S) {
        const int start = tile_prefix + intra_excl;
        const int end   = start + len;
        g_off[s] = start;
        if (s == S - 1) g_off[S] = end;       // sentinel (== N)
        for (int c = (start + 255) >> 8; (c << 8) < end; ++c)
            g_chunkseg[c] = s;
    }
}

// ============================================================
// Kernel 2: one WARP per 256-element chunk (balanced single pass).
// NO tail, NO fences, NO single-address atomics — keep it pure.
// ============================================================
__global__ void __launch_bounds__(256)
main_kernel(const float* __restrict__ means,
            const float* __restrict__ targets,
            int N, int S)
{
    const int lane = threadIdx.x & 31;
    const int warp = (blockIdx.x * 256 + threadIdx.x) >> 5;
    const int base = warp * 256;
    if (base >= N) return;

    int s = g_chunkseg[warp];   // 1 load replaces binary search

    const int pos0 = base + lane * 4;
    const int pos1 = base + 128 + lane * 4;

    float e[8], w[8], d[8];
    if (base + 256 <= N) {
        const float4* tp = reinterpret_cast<const float4*>(targets);
        const float4* mp = reinterpret_cast<const float4*>(means);
        const int q = (base >> 2) + lane;
        float4 t0 = tp[q];        float4 t1 = tp[q + 32];
        float4 m0 = mp[q];        float4 m1 = mp[q + 32];
        float tt[8] = {t0.x,t0.y,t0.z,t0.w, t1.x,t1.y,t1.z,t1.w};
        float mm[8] = {m0.x,m0.y,m0.z,m0.w, m1.x,m1.y,m1.z,m1.w};
        #pragma unroll
        for (int j = 0; j < 8; ++j) {
            e[j] = __expf(tt[j]);
            w[j] = __expf(mm[j]);
            d[j] = e[j] * mm[j];
        }
    } else {
        #pragma unroll
        for (int j = 0; j < 8; ++j) {
            int p = (j < 4) ? (pos0 + j) : (pos1 + j - 4);
            float tv = (p < N) ? targets[p] : 0.f;
            float mv = (p < N) ? means[p]   : 0.f;
            e[j] = __expf(tv);
            w[j] = __expf(mv);
            d[j] = e[j] * mv;
        }
    }

    const int last = min(base + 255, N - 1);
    int lower = g_off[s];
    for (;;) {
        const int next = g_off[s + 1];  // sentinel guarantees validity
        float a = 0.f, b = 0.f, c = 0.f;
        #pragma unroll
        for (int j = 0; j < 8; ++j) {
            const int p = (j < 4) ? (pos0 + j) : (pos1 + j - 4);
            if (p >= lower && p < next) { a += e[j]; b += w[j]; c += d[j]; }
        }
        #pragma unroll
        for (int o = 16; o; o >>= 1) {
            a += __shfl_xor_sync(0xffffffffu, a, o);
            b += __shfl_xor_sync(0xffffffffu, b, o);
            c += __shfl_xor_sync(0xffffffffu, c, o);
        }
        if (lane == 0) {
            atomicAdd(&g_tden[s], (unsigned long long)__double2ll_rn((double)a * SCALE));
            atomicAdd(&g_msum[s], (unsigned long long)__double2ll_rn((double)b * SCALE));
            atomicAdd(&g_dot [s], (unsigned long long)__double2ll_rn((double)c * SCALE));
        }
        if (next > last) break;
        lower = next;
        ++s;
    }
}

// ============================================================
// Kernel 3: per-segment CE (fp32) + deterministic reduce + reset
// ============================================================
__global__ void __launch_bounds__(256)
ce_kernel(float* __restrict__ out, int S)
{
    const int tid  = threadIdx.x;
    const int lane = tid & 31;
    const int wid  = tid >> 5;
    const int seg  = blockIdx.x * 256 + tid;

    float ce = 0.f;
    if (seg < S) {
        long long tdq = (long long)g_tden[seg];
        float td = __ll2float_rn(tdq);                                 // 2^34 scale cancels
        float ms = __ll2float_rn((long long)g_msum[seg]) * INV_SCALE;  // exact pow2 scale
        float dt = __ll2float_rn((long long)g_dot [seg]);
        if (tdq > 0) ce = dt / td - __logf(ms);
        g_tden[seg] = 0ull; g_msum[seg] = 0ull; g_dot[seg] = 0ull;     // reset for next replay
    }

    __shared__ float sm[8];
    float v = ce;
    #pragma unroll
    for (int o = 16; o; o >>= 1) v += __shfl_xor_sync(0xffffffffu, v, o);
    if (lane == 0) sm[wid] = v;
    __syncthreads();
    if (wid == 0) {
        v = (lane < 8) ? sm[lane] : 0.f;
        #pragma unroll
        for (int o = 4; o; o >>= 1) v += __shfl_xor_sync(0xffffffffu, v, o);
        if (lane == 0) {
            atomicAdd(&g_acc, (unsigned long long)__double2ll_rn((double)v * SCALE));
            __threadfence();
            unsigned int prev = atomicAdd(&g_done, 1u);
            if (prev == gridDim.x - 1) {
                unsigned long long tot = atomicAdd(&g_acc, 0ull);
                double sum = (double)(long long)tot / SCALE;
                out[0] = (float)(-sum / (double)S);
                g_acc  = 0ull;   // reset for next replay
                g_done = 0u;
                g_scnt = 0u;     // re-arm scan handshake
                __threadfence();
            }
        }
    }
}

// ============================================================
extern "C" void kernel_launch(void* const* d_in, const int* in_sizes, int n_in,
                              void* d_out, int out_size)
{
    const float* means   = (const float*)d_in[0];
    const int*   scope   = (const int*)  d_in[1];
    const float* targets = (const float*)d_in[2];
    const int N = in_sizes[0];
    const int S = in_sizes[1];

    const int scanBlocks = (S + 1023) / 1024;
    scan_map_kernel<<<scanBlocks, 1024>>>(scope, S, N);

    const int nWarps  = (N + 255) / 256;
    const int nBlocks = (nWarps + 7) / 8;
    main_kernel<<<nBlocks, 256>>>(means, targets, N, S);

    ce_kernel<<<(S + 255) / 256, 256>>>((float*)d_out, S);
}

// round 13
// speedup vs baseline: 3.0299x; 1.0013x over previous
#include <cuda_runtime.h>
#include <float.h>

// -------- scratch (no allocations; zero-init; ce_kernel resets) --------
#define MAXS 32768
#define MAXC 65536
#define MAXB 32                                    // max scan blocks (MAXS/1024)
__device__ int                g_off     [MAXS + 1]; // exclusive prefix sum + sentinel
__device__ int                g_chunkseg[MAXC];     // chunk -> containing segment
__device__ int                g_tilesum [MAXB];     // per-block scope totals
__device__ unsigned long long g_tden[MAXS];         // fixed-point (2^34) Σ e^t
__device__ unsigned long long g_msum[MAXS];         // fixed-point Σ e^m
__device__ unsigned long long g_dot [MAXS];         // fixed-point Σ e^t * m
__device__ unsigned long long g_acc;                // fixed-point global Σ ce
__device__ unsigned int       g_scnt;               // scan phase-1 arrival counter
__device__ unsigned int       g_done;               // finished-block counter (ce)

#define SCALE     17179869184.0   // 2^34
#define INV_SCALE 0x1p-34f        // exact power-of-two

__device__ __forceinline__ unsigned int load_acquire_u32(const unsigned int* p) {
    unsigned int v;
    asm volatile("ld.global.acquire.gpu.b32 %0, [%1];" : "=r"(v) : "l"(p) : "memory");
    return v;
}

// ============================================================
// Kernel 1: multi-block scan + map (PDL primary: triggers at entry
// so main_kernel may launch and overlap its prologue).
// ============================================================
__global__ void __launch_bounds__(1024)
scan_map_kernel(const int* __restrict__ scope, int S, int N)
{
    if (threadIdx.x == 0) cudaTriggerProgrammaticLaunchCompletion();

    __shared__ int s_w[32];
    const int tid  = threadIdx.x;
    const int lane = tid & 31;
    const int wid  = tid >> 5;
    const int b    = blockIdx.x;
    const int s    = b * 1024 + tid;
    const int B    = gridDim.x;

    // ---- phase 1: intra-block exclusive scan ----
    const int len = (s < S) ? scope[s] : 0;

    int x = len;
    #pragma unroll
    for (int off = 1; off < 32; off <<= 1) {
        int y = __shfl_up_sync(0xffffffffu, x, off);
        if (lane >= off) x += y;
    }
    if (lane == 31) s_w[wid] = x;
    __syncthreads();
    if (wid == 0) {
        int w = s_w[lane];
        #pragma unroll
        for (int off = 1; off < 32; off <<= 1) {
            int y = __shfl_up_sync(0xffffffffu, w, off);
            if (lane >= off) w += y;
        }
        s_w[lane] = w;
    }
    __syncthreads();

    const int intra_excl = ((wid == 0) ? 0 : s_w[wid - 1]) + (x - len);
    const int block_tot  = s_w[31];

    if (tid == 0) {
        g_tilesum[b] = block_tot;
        __threadfence();                 // release (once per block)
        atomicAdd(&g_scnt, 1u);
    }

    // ---- sync: wait for all tile totals (16 pollers, co-resident) ----
    if (tid == 0) {
        while (load_acquire_u32(&g_scnt) < (unsigned int)B) { __nanosleep(64); }
    }
    __syncthreads();

    // ---- phase 2: global offset + map fill ----
    int tile_prefix = 0;
    for (int j = 0; j < b; ++j) tile_prefix += g_tilesum[j];   // <=31 L1-broadcast reads

    if (s < S) {
        const int start = tile_prefix + intra_excl;
        const int end   = start + len;
        g_off[s] = start;
        if (s == S - 1) g_off[S] = end;       // sentinel (== N)
        for (int c = (start + 255) >> 8; (c << 8) < end; ++c)
            g_chunkseg[c] = s;
    }
}

// ============================================================
// Kernel 2: one WARP per 256-element chunk. PDL secondary:
// prologue (loads+exp) is offset-independent and overlaps
// scan_map; hardware grid-dependency sync before bucketing.
// Also PDL primary for ce_kernel (triggers at entry).
// ============================================================
__global__ void __launch_bounds__(256)
main_kernel(const float* __restrict__ means,
            const float* __restrict__ targets,
            int N, int S)
{
    if (threadIdx.x == 0) cudaTriggerProgrammaticLaunchCompletion();

    const int lane = threadIdx.x & 31;
    const int warp = (blockIdx.x * 256 + threadIdx.x) >> 5;
    const int base = warp * 256;

    const int pos0 = base + lane * 4;
    const int pos1 = base + 128 + lane * 4;

    // -------- prologue: independent of scan output --------
    float e[8], w[8], d[8];
    const bool active = (base < N);
    if (active) {
        if (base + 256 <= N) {
            const float4* tp = reinterpret_cast<const float4*>(targets);
            const float4* mp = reinterpret_cast<const float4*>(means);
            const int q = (base >> 2) + lane;
            float4 t0 = tp[q];        float4 t1 = tp[q + 32];
            float4 m0 = mp[q];        float4 m1 = mp[q + 32];
            float tt[8] = {t0.x,t0.y,t0.z,t0.w, t1.x,t1.y,t1.z,t1.w};
            float mm[8] = {m0.x,m0.y,m0.z,m0.w, m1.x,m1.y,m1.z,m1.w};
            #pragma unroll
            for (int j = 0; j < 8; ++j) {
                e[j] = __expf(tt[j]);
                w[j] = __expf(mm[j]);
                d[j] = e[j] * mm[j];
            }
        } else {
            #pragma unroll
            for (int j = 0; j < 8; ++j) {
                int p = (j < 4) ? (pos0 + j) : (pos1 + j - 4);
                float tv = (p < N) ? targets[p] : 0.f;
                float mv = (p < N) ? means[p]   : 0.f;
                e[j] = __expf(tv);
                w[j] = __expf(mv);
                d[j] = e[j] * mv;
            }
        }
    }

    // -------- hardware wait for scan_map grid completion --------
    cudaGridDependencySynchronize();

    if (!active) return;

    int s = g_chunkseg[warp];   // 1 load replaces binary search

    const int last = min(base + 255, N - 1);
    int lower = g_off[s];
    for (;;) {
        const int next = g_off[s + 1];  // sentinel guarantees validity
        float a = 0.f, b = 0.f, c = 0.f;
        #pragma unroll
        for (int j = 0; j < 8; ++j) {
            const int p = (j < 4) ? (pos0 + j) : (pos1 + j - 4);
            if (p >= lower && p < next) { a += e[j]; b += w[j]; c += d[j]; }
        }
        #pragma unroll
        for (int o = 16; o; o >>= 1) {
            a += __shfl_xor_sync(0xffffffffu, a, o);
            b += __shfl_xor_sync(0xffffffffu, b, o);
            c += __shfl_xor_sync(0xffffffffu, c, o);
        }
        if (lane == 0) {
            atomicAdd(&g_tden[s], (unsigned long long)__double2ll_rn((double)a * SCALE));
            atomicAdd(&g_msum[s], (unsigned long long)__double2ll_rn((double)b * SCALE));
            atomicAdd(&g_dot [s], (unsigned long long)__double2ll_rn((double)c * SCALE));
        }
        if (next > last) break;
        lower = next;
        ++s;
    }
}

// ============================================================
// Kernel 3: per-segment CE (fp32) + deterministic reduce + reset.
// PDL secondary: launches during main, waits in hardware.
// ============================================================
__global__ void __launch_bounds__(256)
ce_kernel(float* __restrict__ out, int S)
{
    cudaGridDependencySynchronize();   // wait for main_kernel's memory

    const int tid  = threadIdx.x;
    const int lane = tid & 31;
    const int wid  = tid >> 5;
    const int seg  = blockIdx.x * 256 + tid;

    float ce = 0.f;
    if (seg < S) {
        long long tdq = (long long)g_tden[seg];
        float td = __ll2float_rn(tdq);                                 // 2^34 scale cancels
        float ms = __ll2float_rn((long long)g_msum[seg]) * INV_SCALE;  // exact pow2 scale
        float dt = __ll2float_rn((long long)g_dot [seg]);
        if (tdq > 0) ce = dt / td - __logf(ms);
        g_tden[seg] = 0ull; g_msum[seg] = 0ull; g_dot[seg] = 0ull;     // reset for next replay
    }

    __shared__ float sm[8];
    float v = ce;
    #pragma unroll
    for (int o = 16; o; o >>= 1) v += __shfl_xor_sync(0xffffffffu, v, o);
    if (lane == 0) sm[wid] = v;
    __syncthreads();
    if (wid == 0) {
        v = (lane < 8) ? sm[lane] : 0.f;
        #pragma unroll
        for (int o = 4; o; o >>= 1) v += __shfl_xor_sync(0xffffffffu, v, o);
        if (lane == 0) {
            atomicAdd(&g_acc, (unsigned long long)__double2ll_rn((double)v * SCALE));
            __threadfence();
            unsigned int prev = atomicAdd(&g_done, 1u);
            if (prev == gridDim.x - 1) {
                unsigned long long tot = atomicAdd(&g_acc, 0ull);
                double sum = (double)(long long)tot / SCALE;
                out[0] = (float)(-sum / (double)S);
                g_acc  = 0ull;   // reset for next replay
                g_done = 0u;
                g_scnt = 0u;     // re-arm scan handshake
                __threadfence();
            }
        }
    }
}

// ============================================================
extern "C" void kernel_launch(void* const* d_in, const int* in_sizes, int n_in,
                              void* d_out, int out_size)
{
    const float* means   = (const float*)d_in[0];
    const int*   scope   = (const int*)  d_in[1];
    const float* targets = (const float*)d_in[2];
    const int N = in_sizes[0];
    const int S = in_sizes[1];

    const int scanBlocks = (S + 1023) / 1024;
    scan_map_kernel<<<scanBlocks, 1024>>>(scope, S, N);

    // main_kernel: PDL secondary of scan_map
    {
        cudaLaunchConfig_t cfg = {};
        const int nWarps  = (N + 255) / 256;
        cfg.gridDim  = dim3((nWarps + 7) / 8, 1, 1);
        cfg.blockDim = dim3(256, 1, 1);
        cfg.stream   = 0;
        cudaLaunchAttribute attr[1];
        attr[0].id = cudaLaunchAttributeProgrammaticStreamSerialization;
        attr[0].val.programmaticStreamSerializationAllowed = 1;
        cfg.attrs    = attr;
        cfg.numAttrs = 1;
        cudaLaunchKernelEx(&cfg, main_kernel, means, targets, N, S);
    }

    // ce_kernel: PDL secondary of main_kernel
    {
        cudaLaunchConfig_t cfg = {};
        cfg.gridDim  = dim3((S + 255) / 256, 1, 1);
        cfg.blockDim = dim3(256, 1, 1);
        cfg.stream   = 0;
        cudaLaunchAttribute attr[1];
        attr[0].id = cudaLaunchAttributeProgrammaticStreamSerialization;
        attr[0].val.programmaticStreamSerializationAllowed = 1;
        cfg.attrs    = attr;
        cfg.numAttrs = 1;
        cudaLaunchKernelEx(&cfg, ce_kernel, (float*)d_out, S);
    }
}